// round 6
// baseline (speedup 1.0000x reference)
#include <cuda_runtime.h>
#include <cuda_fp16.h>
#include <stdint.h>
#include <stddef.h>

// ---------------------------------------------------------------------------
// out0 = normalize_rows(x) @ features^T   [2048 x 100000]  (fp32)
// out1 = features (passthrough)           [100000 x 256]
// Round 5: fp16 2-product split GEMM via mma.sync.
//   C = (A_hi + A_lo) * B_fp16 ; only B's fp16 rounding contributes error.
//   48KB/stage x2 stages = 96KB smem -> 2 CTAs/SM for latency hiding.
// ---------------------------------------------------------------------------

#define MROWS 2048
#define KDIM  256
#define NPAD  100096      // 782 * 128

#define BM 128
#define BN 128
#define BK 64
#define NCHUNK 4          // K / BK

// smem: 3 tiles of [128 rows][64 fp16 = 128B] = 16KB each, 2 stages
#define T_AHI 0
#define T_ALO 16384
#define T_B   32768
#define STAGE 49152
#define SMEM_TOTAL (2 * STAGE)

__device__ __half g_A_hi[MROWS * KDIM];
__device__ __half g_A_lo[MROWS * KDIM];
__device__ __half g_B[(size_t)NPAD * KDIM];

// ------------------------------ helpers -----------------------------------

__device__ __forceinline__ uint32_t smem_u32(const void* p) {
    uint32_t a;
    asm("{ .reg .u64 t; cvta.to.shared.u64 t, %1; cvt.u32.u64 %0, t; }"
        : "=r"(a) : "l"(p));
    return a;
}

__device__ __forceinline__ void cp16(uint32_t dst, const void* src) {
    asm volatile("cp.async.cg.shared.global [%0], [%1], 16;"
                 :: "r"(dst), "l"(src) : "memory");
}
__device__ __forceinline__ void cp_commit() {
    asm volatile("cp.async.commit_group;" ::: "memory");
}

__device__ __forceinline__ void ldmx4(uint32_t* f, uint32_t addr) {
    asm volatile("ldmatrix.sync.aligned.m8n8.x4.shared.b16 {%0,%1,%2,%3}, [%4];"
                 : "=r"(f[0]), "=r"(f[1]), "=r"(f[2]), "=r"(f[3]) : "r"(addr));
}

#define MMA(c, a, b)                                                          \
    asm volatile(                                                             \
        "mma.sync.aligned.m16n8k16.row.col.f32.f16.f16.f32 "                  \
        "{%0,%1,%2,%3},{%4,%5,%6,%7},{%8,%9},{%0,%1,%2,%3};"                  \
        : "+f"((c)[0]), "+f"((c)[1]), "+f"((c)[2]), "+f"((c)[3])              \
        : "r"((a)[0]), "r"((a)[1]), "r"((a)[2]), "r"((a)[3]),                 \
          "r"((b)[0]), "r"((b)[1]))

// Swizzled byte offset for 16B-unit (r, u) in a [128][64] fp16 tile (128B rows).
__device__ __forceinline__ uint32_t swz(int r, int u) {
    return (uint32_t)(r * 128 + ((u ^ (r & 7)) << 4));
}

// Load one [128][64] fp16 tile (chunk c of K) into smem with swizzle.
__device__ __forceinline__ void load_tile(uint32_t sdst, const __half* g,
                                          int row0, int c, int tid) {
    #pragma unroll
    for (int j = 0; j < 4; j++) {
        int id = j * 256 + tid;          // 0..1023 16B-units
        int r = id >> 3, u = id & 7;
        const __half* src = g + (size_t)(row0 + r) * KDIM + c * BK + u * 8;
        cp16(sdst + swz(r, u), src);
    }
}

// --------------------------- prep kernels ---------------------------------

__global__ void normalize_split_kernel(const float* __restrict__ x) {
    int row = blockIdx.x;
    int t = threadIdx.x;                    // 0..63
    float4 v = ((const float4*)(x + (size_t)row * KDIM))[t];
    float s = v.x * v.x + v.y * v.y + v.z * v.z + v.w * v.w;
    #pragma unroll
    for (int o = 16; o > 0; o >>= 1) s += __shfl_xor_sync(0xffffffffu, s, o);
    __shared__ float ws[2];
    if ((t & 31) == 0) ws[t >> 5] = s;
    __syncthreads();
    float nrm = sqrtf(ws[0] + ws[1]);
    float inv = 1.0f / fmaxf(nrm, 1e-12f);
    float xs[4] = {v.x * inv, v.y * inv, v.z * inv, v.w * inv};
    __half hi[4], lo[4];
    #pragma unroll
    for (int j = 0; j < 4; j++) {
        hi[j] = __float2half_rn(xs[j]);
        lo[j] = __float2half_rn(xs[j] - __half2float(hi[j]));
    }
    size_t base = (size_t)row * KDIM + t * 4;
    __half2* h2 = (__half2*)(g_A_hi + base);
    __half2* l2 = (__half2*)(g_A_lo + base);
    h2[0] = __halves2half2(hi[0], hi[1]);
    h2[1] = __halves2half2(hi[2], hi[3]);
    l2[0] = __halves2half2(lo[0], lo[1]);
    l2[1] = __halves2half2(lo[2], lo[3]);
}

// Convert features to fp16 + fused fp32 passthrough copy; zero pad rows.
__global__ void feat_split_kernel(const float* __restrict__ f,
                                  float* __restrict__ fcopy,
                                  long total4, long total4p) {
    long i = (long)blockIdx.x * blockDim.x + threadIdx.x;
    if (i >= total4p) return;
    __half2* h2 = (__half2*)g_B;
    if (i >= total4) {
        __half2 z = __halves2half2(__float2half(0.f), __float2half(0.f));
        h2[2 * i] = z; h2[2 * i + 1] = z;
        return;
    }
    float4 v = ((const float4*)f)[i];
    ((float4*)fcopy)[i] = v;
    h2[2 * i + 0] = __halves2half2(__float2half_rn(v.x), __float2half_rn(v.y));
    h2[2 * i + 1] = __halves2half2(__float2half_rn(v.z), __float2half_rn(v.w));
}

// ------------------------------ GEMM kernel -------------------------------

__global__ __launch_bounds__(256, 2)
void gemm_mma(float* __restrict__ C, int N) {
    extern __shared__ __align__(128) char smem[];
    uint32_t sb = smem_u32(smem);

    const int tid = threadIdx.x;
    const int lane = tid & 31;
    const int wid = tid >> 5;
    const int m0 = blockIdx.x * BM;      // m fastest -> B tile L2 reuse
    const int n0 = blockIdx.y * BN;
    const int am = (wid & 1) * 64;       // warp m-offset in tile
    const int bn = (wid >> 1) * 32;      // warp n-offset in tile
    const int lr = lane & 7;
    const int q  = lane >> 3;

    float acc[4][4][4];
    #pragma unroll
    for (int mt = 0; mt < 4; mt++)
        #pragma unroll
        for (int nt = 0; nt < 4; nt++)
            #pragma unroll
            for (int e = 0; e < 4; e++) acc[mt][nt][e] = 0.0f;

    // prologue: chunks 0,1 into stages 0,1
    #pragma unroll
    for (int c = 0; c < 2; c++) {
        uint32_t st = sb + c * STAGE;
        load_tile(st + T_AHI, g_A_hi, m0, c, tid);
        load_tile(st + T_ALO, g_A_lo, m0, c, tid);
        load_tile(st + T_B,   g_B,   n0, c, tid);
        cp_commit();
    }

    #pragma unroll
    for (int c = 0; c < NCHUNK; c++) {
        if (c < NCHUNK - 1)
            asm volatile("cp.async.wait_group 1;" ::: "memory");
        else
            asm volatile("cp.async.wait_group 0;" ::: "memory");
        __syncthreads();

        uint32_t st = sb + (c & 1) * STAGE;
        uint32_t sAh = st + T_AHI, sAl = st + T_ALO, sB = st + T_B;

        #pragma unroll
        for (int ks = 0; ks < 4; ks++) {
            uint32_t aH[4][4], aL[4][4];
            #pragma unroll
            for (int mt = 0; mt < 4; mt++) {
                int r = am + mt * 16 + ((q & 1) << 3) + lr;
                int u = ks * 2 + (q >> 1);
                uint32_t off = swz(r, u);
                ldmx4(aH[mt], sAh + off);
                ldmx4(aL[mt], sAl + off);
            }
            uint32_t bF[2][4];
            #pragma unroll
            for (int np = 0; np < 2; np++) {
                int r = bn + np * 16 + ((q >> 1) << 3) + lr;
                int u = ks * 2 + (q & 1);
                ldmx4(bF[np], sB + swz(r, u));
            }
            #pragma unroll
            for (int mt = 0; mt < 4; mt++) {
                #pragma unroll
                for (int nt = 0; nt < 4; nt++) {
                    uint32_t* b = &bF[nt >> 1][(nt & 1) * 2];
                    MMA(acc[mt][nt], aH[mt], b);
                    MMA(acc[mt][nt], aL[mt], b);
                }
            }
        }
        __syncthreads();

        if (c < NCHUNK - 2) {
            uint32_t st2 = sb + (c & 1) * STAGE;
            int c2 = c + 2;
            load_tile(st2 + T_AHI, g_A_hi, m0, c2, tid);
            load_tile(st2 + T_ALO, g_A_lo, m0, c2, tid);
            load_tile(st2 + T_B,   g_B,   n0, c2, tid);
            cp_commit();
        }
    }

    // ---- epilogue: direct stores (fp32) ----
    const int r0 = lane >> 2;
    const int cq = (lane & 3) * 2;
    #pragma unroll
    for (int mt = 0; mt < 4; mt++) {
        #pragma unroll
        for (int nt = 0; nt < 4; nt++) {
            int row = m0 + am + mt * 16 + r0;
            int col = n0 + bn + nt * 8 + cq;
            if (col < N) {
                float2 v0 = make_float2(acc[mt][nt][0], acc[mt][nt][1]);
                float2 v1 = make_float2(acc[mt][nt][2], acc[mt][nt][3]);
                *(float2*)&C[(size_t)row * N + col] = v0;
                *(float2*)&C[(size_t)(row + 8) * N + col] = v1;
            }
        }
    }
}

// ------------------------------ host side ---------------------------------

extern "C" void kernel_launch(void* const* d_in, const int* in_sizes, int n_in,
                              void* d_out, int out_size) {
    const float* x     = (const float*)d_in[0];   // [B, D]
    const float* feats = (const float*)d_in[2];   // [N, D]

    const int Bm = in_sizes[1];            // 2048
    const int D  = in_sizes[0] / Bm;       // 256
    const int N  = in_sizes[2] / D;        // 100000

    float* out = (float*)d_out;
    const size_t featE = (size_t)in_sizes[2];
    const size_t out_off = (size_t)out_size - featE;

    // 1) prep: normalize+split A (fp16 hi/lo), B -> fp16 (+passthrough copy)
    normalize_split_kernel<<<Bm, 64>>>(x);
    long total4  = (long)N * D / 4;
    long total4p = (long)NPAD * D / 4;
    feat_split_kernel<<<(unsigned)((total4p + 255) / 256), 256>>>(
        feats, out + out_off, total4, total4p);

    // 2) GEMM
    static int smem_set = 0;
    if (!smem_set) {
        cudaFuncSetAttribute(gemm_mma, cudaFuncAttributeMaxDynamicSharedMemorySize,
                             SMEM_TOTAL);
        smem_set = 1;
    }
    dim3 grid(Bm / BM, (N + BN - 1) / BN);   // m fastest for B-tile L2 reuse
    gemm_mma<<<grid, 256, SMEM_TOTAL>>>(out, N);
}

// round 7
// speedup vs baseline: 1.5323x; 1.5323x over previous
#include <cuda_runtime.h>
#include <cuda_fp16.h>
#include <stdint.h>
#include <stddef.h>

// ---------------------------------------------------------------------------
// out0 = normalize_rows(x) @ features^T   [2048 x 100000]  (fp32)
// out1 = features (passthrough)           [100000 x 256]
// Round 6: plain fp16 single-product GEMM via mma.sync (fp32 accum).
//   Error = A fp16 rounding (+) B fp16 rounding ~= 2.9e-4 << 1e-3 gate.
//   32KB/stage x2 stages = 64KB smem -> 2 CTAs/SM.
// ---------------------------------------------------------------------------

#define MROWS 2048
#define KDIM  256
#define NPAD  100096      // 782 * 128

#define BM 128
#define BN 128
#define BK 64
#define NCHUNK 4          // K / BK

// smem: 2 tiles of [128 rows][64 fp16 = 128B] = 16KB each, 2 stages
#define T_A 0
#define T_B 16384
#define STAGE 32768
#define SMEM_TOTAL (2 * STAGE)

__device__ __half g_A[MROWS * KDIM];
__device__ __half g_B[(size_t)NPAD * KDIM];

// ------------------------------ helpers -----------------------------------

__device__ __forceinline__ uint32_t smem_u32(const void* p) {
    uint32_t a;
    asm("{ .reg .u64 t; cvta.to.shared.u64 t, %1; cvt.u32.u64 %0, t; }"
        : "=r"(a) : "l"(p));
    return a;
}

__device__ __forceinline__ void cp16(uint32_t dst, const void* src) {
    asm volatile("cp.async.cg.shared.global [%0], [%1], 16;"
                 :: "r"(dst), "l"(src) : "memory");
}
__device__ __forceinline__ void cp_commit() {
    asm volatile("cp.async.commit_group;" ::: "memory");
}

__device__ __forceinline__ void ldmx4(uint32_t* f, uint32_t addr) {
    asm volatile("ldmatrix.sync.aligned.m8n8.x4.shared.b16 {%0,%1,%2,%3}, [%4];"
                 : "=r"(f[0]), "=r"(f[1]), "=r"(f[2]), "=r"(f[3]) : "r"(addr));
}

#define MMA(c, a, b)                                                          \
    asm volatile(                                                             \
        "mma.sync.aligned.m16n8k16.row.col.f32.f16.f16.f32 "                  \
        "{%0,%1,%2,%3},{%4,%5,%6,%7},{%8,%9},{%0,%1,%2,%3};"                  \
        : "+f"((c)[0]), "+f"((c)[1]), "+f"((c)[2]), "+f"((c)[3])              \
        : "r"((a)[0]), "r"((a)[1]), "r"((a)[2]), "r"((a)[3]),                 \
          "r"((b)[0]), "r"((b)[1]))

// Swizzled byte offset for 16B-unit (r, u) in a [128][64] fp16 tile (128B rows).
__device__ __forceinline__ uint32_t swz(int r, int u) {
    return (uint32_t)(r * 128 + ((u ^ (r & 7)) << 4));
}

// Load one [128][64] fp16 tile (chunk c of K) into smem with swizzle.
__device__ __forceinline__ void load_tile(uint32_t sdst, const __half* g,
                                          int row0, int c, int tid) {
    #pragma unroll
    for (int j = 0; j < 4; j++) {
        int id = j * 256 + tid;          // 0..1023 16B-units
        int r = id >> 3, u = id & 7;
        const __half* src = g + (size_t)(row0 + r) * KDIM + c * BK + u * 8;
        cp16(sdst + swz(r, u), src);
    }
}

// --------------------------- prep kernels ---------------------------------

__global__ void normalize_h_kernel(const float* __restrict__ x) {
    int row = blockIdx.x;
    int t = threadIdx.x;                    // 0..63
    float4 v = ((const float4*)(x + (size_t)row * KDIM))[t];
    float s = v.x * v.x + v.y * v.y + v.z * v.z + v.w * v.w;
    #pragma unroll
    for (int o = 16; o > 0; o >>= 1) s += __shfl_xor_sync(0xffffffffu, s, o);
    __shared__ float ws[2];
    if ((t & 31) == 0) ws[t >> 5] = s;
    __syncthreads();
    float nrm = sqrtf(ws[0] + ws[1]);
    float inv = 1.0f / fmaxf(nrm, 1e-12f);
    __half2* h2 = (__half2*)(g_A + (size_t)row * KDIM + t * 4);
    h2[0] = __halves2half2(__float2half_rn(v.x * inv), __float2half_rn(v.y * inv));
    h2[1] = __halves2half2(__float2half_rn(v.z * inv), __float2half_rn(v.w * inv));
}

// Convert features to fp16 + fused fp32 passthrough copy; zero pad rows.
__global__ void feat_h_kernel(const float* __restrict__ f,
                              float* __restrict__ fcopy,
                              long total4, long total4p) {
    long i = (long)blockIdx.x * blockDim.x + threadIdx.x;
    if (i >= total4p) return;
    __half2* h2 = (__half2*)g_B;
    if (i >= total4) {
        __half2 z = __halves2half2(__float2half(0.f), __float2half(0.f));
        h2[2 * i] = z; h2[2 * i + 1] = z;
        return;
    }
    float4 v = ((const float4*)f)[i];
    ((float4*)fcopy)[i] = v;
    h2[2 * i + 0] = __halves2half2(__float2half_rn(v.x), __float2half_rn(v.y));
    h2[2 * i + 1] = __halves2half2(__float2half_rn(v.z), __float2half_rn(v.w));
}

// ------------------------------ GEMM kernel -------------------------------

__global__ __launch_bounds__(256, 2)
void gemm_mma(float* __restrict__ C, int N) {
    extern __shared__ __align__(128) char smem[];
    uint32_t sb = smem_u32(smem);

    const int tid = threadIdx.x;
    const int lane = tid & 31;
    const int wid = tid >> 5;
    const int m0 = blockIdx.x * BM;      // m fastest -> B tile L2 reuse
    const int n0 = blockIdx.y * BN;
    const int am = (wid & 1) * 64;       // warp m-offset in tile
    const int bn = (wid >> 1) * 32;      // warp n-offset in tile
    const int lr = lane & 7;
    const int q  = lane >> 3;

    float acc[4][4][4];
    #pragma unroll
    for (int mt = 0; mt < 4; mt++)
        #pragma unroll
        for (int nt = 0; nt < 4; nt++)
            #pragma unroll
            for (int e = 0; e < 4; e++) acc[mt][nt][e] = 0.0f;

    // prologue: chunks 0,1 into stages 0,1
    #pragma unroll
    for (int c = 0; c < 2; c++) {
        uint32_t st = sb + c * STAGE;
        load_tile(st + T_A, g_A, m0, c, tid);
        load_tile(st + T_B, g_B, n0, c, tid);
        cp_commit();
    }

    #pragma unroll
    for (int c = 0; c < NCHUNK; c++) {
        if (c < NCHUNK - 1)
            asm volatile("cp.async.wait_group 1;" ::: "memory");
        else
            asm volatile("cp.async.wait_group 0;" ::: "memory");
        __syncthreads();

        uint32_t st = sb + (c & 1) * STAGE;
        uint32_t sA = st + T_A, sB = st + T_B;

        #pragma unroll
        for (int ks = 0; ks < 4; ks++) {
            uint32_t aF[4][4];
            #pragma unroll
            for (int mt = 0; mt < 4; mt++) {
                int r = am + mt * 16 + ((q & 1) << 3) + lr;
                int u = ks * 2 + (q >> 1);
                ldmx4(aF[mt], sA + swz(r, u));
            }
            uint32_t bF[2][4];
            #pragma unroll
            for (int np = 0; np < 2; np++) {
                int r = bn + np * 16 + ((q >> 1) << 3) + lr;
                int u = ks * 2 + (q & 1);
                ldmx4(bF[np], sB + swz(r, u));
            }
            #pragma unroll
            for (int mt = 0; mt < 4; mt++) {
                #pragma unroll
                for (int nt = 0; nt < 4; nt++) {
                    uint32_t* b = &bF[nt >> 1][(nt & 1) * 2];
                    MMA(acc[mt][nt], aF[mt], b);
                }
            }
        }
        __syncthreads();

        if (c < NCHUNK - 2) {
            uint32_t st2 = sb + (c & 1) * STAGE;
            int c2 = c + 2;
            load_tile(st2 + T_A, g_A, m0, c2, tid);
            load_tile(st2 + T_B, g_B, n0, c2, tid);
            cp_commit();
        }
    }

    // ---- epilogue: direct stores (fp32) ----
    const int r0 = lane >> 2;
    const int cq = (lane & 3) * 2;
    #pragma unroll
    for (int mt = 0; mt < 4; mt++) {
        #pragma unroll
        for (int nt = 0; nt < 4; nt++) {
            int row = m0 + am + mt * 16 + r0;
            int col = n0 + bn + nt * 8 + cq;
            if (col < N) {
                float2 v0 = make_float2(acc[mt][nt][0], acc[mt][nt][1]);
                float2 v1 = make_float2(acc[mt][nt][2], acc[mt][nt][3]);
                *(float2*)&C[(size_t)row * N + col] = v0;
                *(float2*)&C[(size_t)(row + 8) * N + col] = v1;
            }
        }
    }
}

// ------------------------------ host side ---------------------------------

extern "C" void kernel_launch(void* const* d_in, const int* in_sizes, int n_in,
                              void* d_out, int out_size) {
    const float* x     = (const float*)d_in[0];   // [B, D]
    const float* feats = (const float*)d_in[2];   // [N, D]

    const int Bm = in_sizes[1];            // 2048
    const int D  = in_sizes[0] / Bm;       // 256
    const int N  = in_sizes[2] / D;        // 100000

    float* out = (float*)d_out;
    const size_t featE = (size_t)in_sizes[2];
    const size_t out_off = (size_t)out_size - featE;

    // 1) prep: normalize A -> fp16, B -> fp16 (+passthrough copy, zero pad)
    normalize_h_kernel<<<Bm, 64>>>(x);
    long total4  = (long)N * D / 4;
    long total4p = (long)NPAD * D / 4;
    feat_h_kernel<<<(unsigned)((total4p + 255) / 256), 256>>>(
        feats, out + out_off, total4, total4p);

    // 2) GEMM
    static int smem_set = 0;
    if (!smem_set) {
        cudaFuncSetAttribute(gemm_mma, cudaFuncAttributeMaxDynamicSharedMemorySize,
                             SMEM_TOTAL);
        smem_set = 1;
    }
    dim3 grid(Bm / BM, (N + BN - 1) / BN);   // m fastest for B-tile L2 reuse
    gemm_mma<<<grid, 256, SMEM_TOTAL>>>(out, N);
}

// round 8
// speedup vs baseline: 1.5752x; 1.0280x over previous
#include <cuda_runtime.h>
#include <cuda_fp16.h>
#include <stdint.h>
#include <stddef.h>

// ---------------------------------------------------------------------------
// out0 = normalize_rows(x) @ features^T   [2048 x 100000]  (fp32)
// out1 = features (passthrough)           [100000 x 256]
// Round 7: fp16 single-product mma.sync GEMM, 3-stage cp.async pipeline,
// early prefetch, one barrier per chunk. 96KB smem/CTA, 2 CTAs/SM.
// ---------------------------------------------------------------------------

#define MROWS 2048
#define KDIM  256
#define NPAD  100096      // 782 * 128

#define BM 128
#define BN 128
#define BK 64
#define NCHUNK 4          // K / BK
#define NSTAGE 3

// smem: 2 tiles of [128 rows][64 fp16 = 128B] = 16KB each, 3 stages
#define T_A 0
#define T_B 16384
#define STAGE 32768
#define SMEM_TOTAL (NSTAGE * STAGE)

__device__ __half g_A[MROWS * KDIM];
__device__ __half g_B[(size_t)NPAD * KDIM];

// ------------------------------ helpers -----------------------------------

__device__ __forceinline__ uint32_t smem_u32(const void* p) {
    uint32_t a;
    asm("{ .reg .u64 t; cvta.to.shared.u64 t, %1; cvt.u32.u64 %0, t; }"
        : "=r"(a) : "l"(p));
    return a;
}

__device__ __forceinline__ void cp16(uint32_t dst, const void* src) {
    asm volatile("cp.async.cg.shared.global [%0], [%1], 16;"
                 :: "r"(dst), "l"(src) : "memory");
}
__device__ __forceinline__ void cp_commit() {
    asm volatile("cp.async.commit_group;" ::: "memory");
}

__device__ __forceinline__ void ldmx4(uint32_t* f, uint32_t addr) {
    asm volatile("ldmatrix.sync.aligned.m8n8.x4.shared.b16 {%0,%1,%2,%3}, [%4];"
                 : "=r"(f[0]), "=r"(f[1]), "=r"(f[2]), "=r"(f[3]) : "r"(addr));
}

#define MMA(c, a, b)                                                          \
    asm volatile(                                                             \
        "mma.sync.aligned.m16n8k16.row.col.f32.f16.f16.f32 "                  \
        "{%0,%1,%2,%3},{%4,%5,%6,%7},{%8,%9},{%0,%1,%2,%3};"                  \
        : "+f"((c)[0]), "+f"((c)[1]), "+f"((c)[2]), "+f"((c)[3])              \
        : "r"((a)[0]), "r"((a)[1]), "r"((a)[2]), "r"((a)[3]),                 \
          "r"((b)[0]), "r"((b)[1]))

// Swizzled byte offset for 16B-unit (r, u) in a [128][64] fp16 tile (128B rows).
__device__ __forceinline__ uint32_t swz(int r, int u) {
    return (uint32_t)(r * 128 + ((u ^ (r & 7)) << 4));
}

// Load one [128][64] fp16 tile (chunk c of K) into smem with swizzle.
__device__ __forceinline__ void load_tile(uint32_t sdst, const __half* g,
                                          int row0, int c, int tid) {
    #pragma unroll
    for (int j = 0; j < 4; j++) {
        int id = j * 256 + tid;          // 0..1023 16B-units
        int r = id >> 3, u = id & 7;
        const __half* src = g + (size_t)(row0 + r) * KDIM + c * BK + u * 8;
        cp16(sdst + swz(r, u), src);
    }
}

// --------------------------- prep kernels ---------------------------------

__global__ void normalize_h_kernel(const float* __restrict__ x) {
    int row = blockIdx.x;
    int t = threadIdx.x;                    // 0..63
    float4 v = ((const float4*)(x + (size_t)row * KDIM))[t];
    float s = v.x * v.x + v.y * v.y + v.z * v.z + v.w * v.w;
    #pragma unroll
    for (int o = 16; o > 0; o >>= 1) s += __shfl_xor_sync(0xffffffffu, s, o);
    __shared__ float ws[2];
    if ((t & 31) == 0) ws[t >> 5] = s;
    __syncthreads();
    float nrm = sqrtf(ws[0] + ws[1]);
    float inv = 1.0f / fmaxf(nrm, 1e-12f);
    __half2* h2 = (__half2*)(g_A + (size_t)row * KDIM + t * 4);
    h2[0] = __halves2half2(__float2half_rn(v.x * inv), __float2half_rn(v.y * inv));
    h2[1] = __halves2half2(__float2half_rn(v.z * inv), __float2half_rn(v.w * inv));
}

// Convert features to fp16 + fused fp32 passthrough copy; zero pad rows.
__global__ void feat_h_kernel(const float* __restrict__ f,
                              float* __restrict__ fcopy,
                              long total4, long total4p) {
    long i = (long)blockIdx.x * blockDim.x + threadIdx.x;
    if (i >= total4p) return;
    __half2* h2 = (__half2*)g_B;
    if (i >= total4) {
        __half2 z = __halves2half2(__float2half(0.f), __float2half(0.f));
        h2[2 * i] = z; h2[2 * i + 1] = z;
        return;
    }
    float4 v = ((const float4*)f)[i];
    ((float4*)fcopy)[i] = v;
    h2[2 * i + 0] = __halves2half2(__float2half_rn(v.x), __float2half_rn(v.y));
    h2[2 * i + 1] = __halves2half2(__float2half_rn(v.z), __float2half_rn(v.w));
}

// ------------------------------ GEMM kernel -------------------------------

__global__ __launch_bounds__(256, 2)
void gemm_mma(float* __restrict__ C, int N) {
    extern __shared__ __align__(128) char smem[];
    uint32_t sb = smem_u32(smem);

    const int tid = threadIdx.x;
    const int lane = tid & 31;
    const int wid = tid >> 5;
    const int m0 = blockIdx.x * BM;      // m fastest -> B tile L2 reuse
    const int n0 = blockIdx.y * BN;
    const int am = (wid & 1) * 64;       // warp m-offset in tile
    const int bn = (wid >> 1) * 32;      // warp n-offset in tile
    const int lr = lane & 7;
    const int q  = lane >> 3;

    float acc[4][4][4];
    #pragma unroll
    for (int mt = 0; mt < 4; mt++)
        #pragma unroll
        for (int nt = 0; nt < 4; nt++)
            #pragma unroll
            for (int e = 0; e < 4; e++) acc[mt][nt][e] = 0.0f;

    // prologue: chunks 0,1 into stages 0,1
    #pragma unroll
    for (int c = 0; c < 2; c++) {
        uint32_t st = sb + c * STAGE;
        load_tile(st + T_A, g_A, m0, c, tid);
        load_tile(st + T_B, g_B, n0, c, tid);
        cp_commit();
    }

    #pragma unroll
    for (int c = 0; c < NCHUNK; c++) {
        // Make chunk c's data visible; keep next prefetch in flight.
        if (c < NCHUNK - 1)
            asm volatile("cp.async.wait_group 1;" ::: "memory");
        else
            asm volatile("cp.async.wait_group 0;" ::: "memory");
        __syncthreads();

        // Early prefetch: chunk c+2 into stage (c+2)%3 (last read in iter c-1,
        // protected by the barrier above). Overlaps the whole compute below.
        if (c < NCHUNK - 2) {
            int c2 = c + 2;
            uint32_t st2 = sb + (c2 % NSTAGE) * STAGE;
            load_tile(st2 + T_A, g_A, m0, c2, tid);
            load_tile(st2 + T_B, g_B, n0, c2, tid);
            cp_commit();
        }

        uint32_t st = sb + (c % NSTAGE) * STAGE;
        uint32_t sA = st + T_A, sB = st + T_B;

        #pragma unroll
        for (int ks = 0; ks < 4; ks++) {
            uint32_t aF[4][4];
            #pragma unroll
            for (int mt = 0; mt < 4; mt++) {
                int r = am + mt * 16 + ((q & 1) << 3) + lr;
                int u = ks * 2 + (q >> 1);
                ldmx4(aF[mt], sA + swz(r, u));
            }
            uint32_t bF[2][4];
            #pragma unroll
            for (int np = 0; np < 2; np++) {
                int r = bn + np * 16 + ((q >> 1) << 3) + lr;
                int u = ks * 2 + (q & 1);
                ldmx4(bF[np], sB + swz(r, u));
            }
            #pragma unroll
            for (int mt = 0; mt < 4; mt++) {
                #pragma unroll
                for (int nt = 0; nt < 4; nt++) {
                    uint32_t* b = &bF[nt >> 1][(nt & 1) * 2];
                    MMA(acc[mt][nt], aF[mt], b);
                }
            }
        }
    }

    // ---- epilogue: direct stores (fp32) ----
    const int r0 = lane >> 2;
    const int cq = (lane & 3) * 2;
    #pragma unroll
    for (int mt = 0; mt < 4; mt++) {
        #pragma unroll
        for (int nt = 0; nt < 4; nt++) {
            int row = m0 + am + mt * 16 + r0;
            int col = n0 + bn + nt * 8 + cq;
            if (col < N) {
                float2 v0 = make_float2(acc[mt][nt][0], acc[mt][nt][1]);
                float2 v1 = make_float2(acc[mt][nt][2], acc[mt][nt][3]);
                *(float2*)&C[(size_t)row * N + col] = v0;
                *(float2*)&C[(size_t)(row + 8) * N + col] = v1;
            }
        }
    }
}

// ------------------------------ host side ---------------------------------

extern "C" void kernel_launch(void* const* d_in, const int* in_sizes, int n_in,
                              void* d_out, int out_size) {
    const float* x     = (const float*)d_in[0];   // [B, D]
    const float* feats = (const float*)d_in[2];   // [N, D]

    const int Bm = in_sizes[1];            // 2048
    const int D  = in_sizes[0] / Bm;       // 256
    const int N  = in_sizes[2] / D;        // 100000

    float* out = (float*)d_out;
    const size_t featE = (size_t)in_sizes[2];
    const size_t out_off = (size_t)out_size - featE;

    // 1) prep: normalize A -> fp16, B -> fp16 (+passthrough copy, zero pad)
    normalize_h_kernel<<<Bm, 64>>>(x);
    long total4  = (long)N * D / 4;
    long total4p = (long)NPAD * D / 4;
    feat_h_kernel<<<(unsigned)((total4p + 255) / 256), 256>>>(
        feats, out + out_off, total4, total4p);

    // 2) GEMM
    static int smem_set = 0;
    if (!smem_set) {
        cudaFuncSetAttribute(gemm_mma, cudaFuncAttributeMaxDynamicSharedMemorySize,
                             SMEM_TOTAL);
        smem_set = 1;
    }
    dim3 grid(Bm / BM, (N + BN - 1) / BN);   // m fastest for B-tile L2 reuse
    gemm_mma<<<grid, 256, SMEM_TOTAL>>>(out, N);
}